// round 4
// baseline (speedup 1.0000x reference)
#include <cuda_runtime.h>
#include <math.h>

#define N_NODES 100000
#define IN_F 256
#define HID 128
#define OUT_F 64
#define E_MAX 1600000
#define SCAN_B 1024
#define SCAN_NB ((N_NODES + SCAN_B - 1) / SCAN_B)   // 98

typedef unsigned long long ull;

// Scratch (device globals — no allocation allowed in kernel_launch).
__device__ float g_msg[(size_t)N_NODES * HID];   // gemm1 out, then gemm2 out
__device__ float g_acc[(size_t)N_NODES * HID];   // relu(h)+bias after agg1
__device__ int   g_deg_src[N_NODES];
__device__ int   g_deg_dst[N_NODES];
__device__ float g_norm[N_NODES];
__device__ int   g_off[N_NODES + 1];
__device__ int   g_cursor[N_NODES];
__device__ int   g_csr[E_MAX];
__device__ int   g_bsum[SCAN_NB];
__device__ int   g_boff[SCAN_NB];

// ---------------------------------------------------------------------------
__device__ __forceinline__ void ffma2(ull& d, ull a, ull b) {
    asm("fma.rn.f32x2 %0, %1, %2, %0;" : "+l"(d) : "l"(a), "l"(b));
}
__device__ __forceinline__ float2 unpk(ull v) {
    float2 r;
    asm("mov.b64 {%0, %1}, %2;" : "=f"(r.x), "=f"(r.y) : "l"(v));
    return r;
}

// ---------------------------------------------------------------------------
__global__ void zero_deg_kernel() {
    int i = blockIdx.x * blockDim.x + threadIdx.x;
    if (i < N_NODES) { g_deg_src[i] = 0; g_deg_dst[i] = 0; }
}

__global__ void hist_kernel(const int* __restrict__ src, const int* __restrict__ dst, int E) {
    int i = blockIdx.x * blockDim.x + threadIdx.x;
    if (i < E) {
        atomicAdd(&g_deg_src[src[i]], 1);
        atomicAdd(&g_deg_dst[dst[i]], 1);
    }
}

__global__ void scan1_kernel() {
    __shared__ int sh[SCAN_B];
    int tid = threadIdx.x;
    int i = blockIdx.x * SCAN_B + tid;
    int v = (i < N_NODES) ? g_deg_dst[i] : 0;
    sh[tid] = v;
    __syncthreads();
    for (int off = 1; off < SCAN_B; off <<= 1) {
        int t = (tid >= off) ? sh[tid - off] : 0;
        __syncthreads();
        sh[tid] += t;
        __syncthreads();
    }
    if (i < N_NODES) g_off[i] = sh[tid] - v;        // exclusive within block
    if (tid == SCAN_B - 1) g_bsum[blockIdx.x] = sh[tid];
}

__global__ void scan2_kernel() {
    __shared__ int sh[128];
    int tid = threadIdx.x;
    int v = (tid < SCAN_NB) ? g_bsum[tid] : 0;
    sh[tid] = v;
    __syncthreads();
    for (int off = 1; off < 128; off <<= 1) {
        int t = (tid >= off) ? sh[tid - off] : 0;
        __syncthreads();
        sh[tid] += t;
        __syncthreads();
    }
    if (tid < SCAN_NB) g_boff[tid] = sh[tid] - v;
}

__global__ void scan3_kernel(int E) {
    int i = blockIdx.x * blockDim.x + threadIdx.x;
    if (i < N_NODES) {
        int off = g_off[i] + g_boff[i / SCAN_B];
        g_off[i] = off;
        g_cursor[i] = off;
        g_norm[i] = 1.0f / fmaxf((float)g_deg_src[i], 1.0f);
    }
    if (i == 0) g_off[N_NODES] = E;
}

__global__ void scatter_kernel(const int* __restrict__ src, const int* __restrict__ dst, int E) {
    int i = blockIdx.x * blockDim.x + threadIdx.x;
    if (i < E) {
        int pos = atomicAdd(&g_cursor[dst[i]], 1);
        g_csr[pos] = src[i];
    }
}

// ---------------------------------------------------------------------------
// Packed-f32x2 GEMM core. 128x128 block tile, 256 threads, 8x8 microtile.
// As: k-major [kk][row] (row pairs load as b64 -> natural f32x2 over rows).
// Bs2: duplicated {b,b} pairs, chunk-major so each thread's 16B are contiguous
//      across the 16 tx threads of a phase (conflict-free LDS.128).
//      Layout: Bs2[kk][chunk*64 + tx*4], chunk 0..3;
//      chunk c holds j = (c&2 ? 64 : 0) + 4*tx + (c&1)*2 + {0,1} as {b,b,b,b'}.
template <int KTILES, bool A_GLOBAL>
__device__ __forceinline__ void gemm_core(
    const float* __restrict__ Asrc, int lda,
    ull accp[4][8], float* As, float* Bs2,
    int row0, int tid, int tx, int ty,
    const float* __restrict__ W0, const float* __restrict__ W1, int ldw, int wsplit)
{
#pragma unroll 1
    for (int kt = 0; kt < KTILES; kt++) {
        int k0 = kt * 16;
#pragma unroll
        for (int i = 0; i < 2; i++) {          // A tile: 512 float4
            int p = tid + i * 256;
            int r = p >> 2;
            int kk = (p & 3) << 2;
            int grow = row0 + r;
            float4 v = make_float4(0.f, 0.f, 0.f, 0.f);
            if (grow < N_NODES)
                v = *(const float4*)(Asrc + (size_t)grow * lda + k0 + kk);
            As[(kk + 0) * 132 + r] = v.x; As[(kk + 1) * 132 + r] = v.y;
            As[(kk + 2) * 132 + r] = v.z; As[(kk + 3) * 132 + r] = v.w;
        }
#pragma unroll
        for (int i = 0; i < 2; i++) {          // B tile, duplicated pairs
            int p = tid + i * 256;
            int kr = p >> 5;
            int c4 = (p & 31) << 2;            // j base 0..124
            const float* srcw = (c4 < wsplit)
                ? (W0 + (size_t)(k0 + kr) * ldw + c4)
                : (W1 + (size_t)(k0 + kr) * ldw + (c4 - wsplit));
            float4 w = *(const float4*)srcw;
            int t = (c4 & 63) >> 2;
            int cb = (c4 < 64) ? 0 : 2;
            float4 d0 = make_float4(w.x, w.x, w.y, w.y);
            float4 d1 = make_float4(w.z, w.z, w.w, w.w);
            *(float4*)&Bs2[kr * 260 + (cb + 0) * 64 + t * 4] = d0;
            *(float4*)&Bs2[kr * 260 + (cb + 1) * 64 + t * 4] = d1;
        }
        __syncthreads();
#pragma unroll
        for (int kk = 0; kk < 16; kk++) {
            ulonglong2 a01 = *(const ulonglong2*)&As[kk * 132 + ty * 4];
            ulonglong2 a23 = *(const ulonglong2*)&As[kk * 132 + ty * 4 + 64];
            ull ap[4] = { a01.x, a01.y, a23.x, a23.y };
            ull bd[8];
#pragma unroll
            for (int c = 0; c < 4; c++) {
                ulonglong2 bv = *(const ulonglong2*)&Bs2[kk * 260 + c * 64 + tx * 4];
                bd[2 * c + 0] = bv.x;
                bd[2 * c + 1] = bv.y;
            }
#pragma unroll
            for (int ip = 0; ip < 4; ip++)
#pragma unroll
                for (int jj = 0; jj < 8; jj++)
                    ffma2(accp[ip][jj], ap[ip], bd[jj]);
        }
        __syncthreads();
    }
}

__device__ __forceinline__ void gemm_epilogue(
    ull accp[4][8], int row0, int tx, int ty, float* __restrict__ outbuf)
{
#pragma unroll
    for (int ip = 0; ip < 4; ip++) {
        float2 pj[8];
#pragma unroll
        for (int jj = 0; jj < 8; jj++) pj[jj] = unpk(accp[ip][jj]);
#pragma unroll
        for (int lane = 0; lane < 2; lane++) {
            int grow = row0 + ((ip < 2) ? (ty * 4 + ip * 2 + lane)
                                        : (64 + ty * 4 + (ip - 2) * 2 + lane));
            if (grow >= N_NODES) continue;
            float nv = g_norm[grow];
            float o[8];
#pragma unroll
            for (int jj = 0; jj < 8; jj++) o[jj] = (lane ? pj[jj].y : pj[jj].x) * nv;
            *(float4*)(outbuf + (size_t)grow * HID + tx * 4) =
                make_float4(o[0], o[1], o[2], o[3]);
            *(float4*)(outbuf + (size_t)grow * HID + tx * 4 + 64) =
                make_float4(o[4], o[5], o[6], o[7]);
        }
    }
}

// GEMM1: g_msg = (feat @ W_shared) * norm
__global__ __launch_bounds__(256, 2)
void gemm1_kernel(const float* __restrict__ A, const float* __restrict__ W) {
    __shared__ float As[16 * 132];
    __shared__ float Bs2[16 * 260];
    const int tid = threadIdx.x;
    const int tx = tid & 15, ty = tid >> 4;
    const int row0 = blockIdx.x * 128;
    ull accp[4][8];
#pragma unroll
    for (int i = 0; i < 4; i++)
#pragma unroll
        for (int j = 0; j < 8; j++) accp[i][j] = 0ull;
    gemm_core<IN_F / 16, true>(A, IN_F, accp, As, Bs2, row0, tid, tx, ty,
                               W, W, HID, 1 << 30);
    gemm_epilogue(accp, row0, tx, ty, g_msg);
}

// GEMM2 (fused heads): A = g_acc (already relu+bias), B = [W_mu | W_ls]
__global__ __launch_bounds__(256, 2)
void gemm2_kernel(const float* __restrict__ Wmu, const float* __restrict__ Wls) {
    __shared__ float As[16 * 132];
    __shared__ float Bs2[16 * 260];
    const int tid = threadIdx.x;
    const int tx = tid & 15, ty = tid >> 4;
    const int row0 = blockIdx.x * 128;
    ull accp[4][8];
#pragma unroll
    for (int i = 0; i < 4; i++)
#pragma unroll
        for (int j = 0; j < 8; j++) accp[i][j] = 0ull;
    gemm_core<HID / 16, false>(g_acc, HID, accp, As, Bs2, row0, tid, tx, ty,
                               Wmu, Wls, OUT_F, 64);
    gemm_epilogue(accp, row0, tx, ty, g_msg);
}

// ---------------------------------------------------------------------------
// CSR aggregation, one warp per destination node; lane owns cols [4L, 4L+4).
__device__ __forceinline__ float4 warp_gather_sum(int n, int lane) {
    int beg = g_off[n];
    int end = g_off[n + 1];
    float4 acc = make_float4(0.f, 0.f, 0.f, 0.f);
    for (int base = beg; base < end; base += 32) {
        int idx = base + lane;
        int eid = (idx < end) ? g_csr[idx] : 0;
        int cnt = min(32, end - base);
        for (int k = 0; k < cnt; k++) {
            int s = __shfl_sync(0xffffffffu, eid, k);
            float4 v = *(const float4*)(g_msg + (size_t)s * HID + lane * 4);
            acc.x += v.x; acc.y += v.y; acc.z += v.z; acc.w += v.w;
        }
    }
    return acc;
}

// agg pass 1: g_acc[n,:] = relu(sum + b_shared)
__global__ void agg1_kernel(const float* __restrict__ bsh) {
    int n = (int)(((size_t)blockIdx.x * blockDim.x + threadIdx.x) >> 5);
    int lane = threadIdx.x & 31;
    if (n >= N_NODES) return;
    float4 acc = warp_gather_sum(n, lane);
    float4 bb = *(const float4*)(bsh + lane * 4);
    float4 o;
    o.x = fmaxf(acc.x + bb.x, 0.f);
    o.y = fmaxf(acc.y + bb.y, 0.f);
    o.z = fmaxf(acc.z + bb.z, 0.f);
    o.w = fmaxf(acc.w + bb.w, 0.f);
    *(float4*)(g_acc + (size_t)n * HID + lane * 4) = o;
}

// agg pass 2 + reparameterize: lanes 0-15 hold mu cols, 16-31 hold ls cols.
__global__ void agg2_final_kernel(const float* __restrict__ noise,
                                  const float* __restrict__ bmu,
                                  const float* __restrict__ bls,
                                  float* __restrict__ out) {
    int n = (int)(((size_t)blockIdx.x * blockDim.x + threadIdx.x) >> 5);
    int lane = threadIdx.x & 31;
    if (n >= N_NODES) return;
    float4 acc = warp_gather_sum(n, lane);
    float4 other;
    other.x = __shfl_xor_sync(0xffffffffu, acc.x, 16);
    other.y = __shfl_xor_sync(0xffffffffu, acc.y, 16);
    other.z = __shfl_xor_sync(0xffffffffu, acc.z, 16);
    other.w = __shfl_xor_sync(0xffffffffu, acc.w, 16);
    if (lane < 16) {
        int j = lane * 4;
        float4 bm = *(const float4*)(bmu + j);
        float4 bl = *(const float4*)(bls + j);
        float4 nz = *(const float4*)(noise + (size_t)n * OUT_F + j);
        float4 o;
        o.x = acc.x + bm.x + nz.x * expf(other.x + bl.x);
        o.y = acc.y + bm.y + nz.y * expf(other.y + bl.y);
        o.z = acc.z + bm.z + nz.z * expf(other.z + bl.z);
        o.w = acc.w + bm.w + nz.w * expf(other.w + bl.w);
        *(float4*)(out + (size_t)n * OUT_F + j) = o;
    }
}

// ---------------------------------------------------------------------------
extern "C" void kernel_launch(void* const* d_in, const int* in_sizes, int n_in,
                              void* d_out, int out_size) {
    const float* feat  = (const float*)d_in[0];
    const float* Wsh   = (const float*)d_in[1];
    const float* bsh   = (const float*)d_in[2];
    const float* Wmu   = (const float*)d_in[3];
    const float* bmu   = (const float*)d_in[4];
    const float* Wls   = (const float*)d_in[5];
    const float* bls   = (const float*)d_in[6];
    const float* noise = (const float*)d_in[7];
    const int*   src   = (const int*)d_in[8];
    const int*   dst   = (const int*)d_in[9];
    const int E = in_sizes[8];
    float* out = (float*)d_out;

    const int agg_blocks = (N_NODES * 32 + 255) / 256;   // warp per node

    zero_deg_kernel<<<(N_NODES + 255) / 256, 256>>>();
    hist_kernel<<<(E + 255) / 256, 256>>>(src, dst, E);
    scan1_kernel<<<SCAN_NB, SCAN_B>>>();
    scan2_kernel<<<1, 128>>>();
    scan3_kernel<<<(N_NODES + 255) / 256, 256>>>(E);
    scatter_kernel<<<(E + 255) / 256, 256>>>(src, dst, E);
    gemm1_kernel<<<(N_NODES + 127) / 128, 256>>>(feat, Wsh);
    agg1_kernel<<<agg_blocks, 256>>>(bsh);
    gemm2_kernel<<<(N_NODES + 127) / 128, 256>>>(Wmu, Wls);
    agg2_final_kernel<<<agg_blocks, 256>>>(noise, bmu, bls, out);
}

// round 6
// speedup vs baseline: 1.3528x; 1.3528x over previous
#include <cuda_runtime.h>
#include <cuda_bf16.h>
#include <mma.h>
#include <math.h>
#include <cstdint>

using namespace nvcuda;

#define N_NODES 100000
#define IN_F 256
#define HID 128
#define OUT_F 64
#define E_MAX 1600000
#define SCAN_B 1024
#define SCAN_NB ((N_NODES + SCAN_B - 1) / SCAN_B)   // 98

// Scratch (device globals — no allocation allowed in kernel_launch).
__device__ float g_msg[(size_t)N_NODES * HID];   // gemm1 out, then gemm2 out
__device__ float g_acc[(size_t)N_NODES * HID];   // relu(h)+bias after agg1
__device__ int   g_deg_src[N_NODES];
__device__ int   g_deg_dst[N_NODES];
__device__ float g_norm[N_NODES];
__device__ int   g_off[N_NODES + 1];
__device__ int   g_cursor[N_NODES];
__device__ int   g_csr[E_MAX];
__device__ int   g_bsum[SCAN_NB];
__device__ int   g_boff[SCAN_NB];
// Pre-split transposed weights, [N, K] K-contiguous bf16 (wmma B col_major layout)
__device__ __nv_bfloat16 g_w1hi[HID * IN_F];
__device__ __nv_bfloat16 g_w1lo[HID * IN_F];
__device__ __nv_bfloat16 g_w2hi[HID * HID];
__device__ __nv_bfloat16 g_w2lo[HID * HID];

__device__ __forceinline__ uint32_t pack_bf16x2(float a, float b) {
    __nv_bfloat162 h = __floats2bfloat162_rn(a, b);
    return *reinterpret_cast<uint32_t*>(&h);
}

// ---------------------------------------------------------------------------
// Graph preprocessing (unchanged from R3)
// ---------------------------------------------------------------------------
__global__ void zero_deg_kernel() {
    int i = blockIdx.x * blockDim.x + threadIdx.x;
    if (i < N_NODES) { g_deg_src[i] = 0; g_deg_dst[i] = 0; }
}

__global__ void hist_kernel(const int* __restrict__ src, const int* __restrict__ dst, int E) {
    int i = blockIdx.x * blockDim.x + threadIdx.x;
    if (i < E) {
        atomicAdd(&g_deg_src[src[i]], 1);
        atomicAdd(&g_deg_dst[dst[i]], 1);
    }
}

__global__ void scan1_kernel() {
    __shared__ int sh[SCAN_B];
    int tid = threadIdx.x;
    int i = blockIdx.x * SCAN_B + tid;
    int v = (i < N_NODES) ? g_deg_dst[i] : 0;
    sh[tid] = v;
    __syncthreads();
    for (int off = 1; off < SCAN_B; off <<= 1) {
        int t = (tid >= off) ? sh[tid - off] : 0;
        __syncthreads();
        sh[tid] += t;
        __syncthreads();
    }
    if (i < N_NODES) g_off[i] = sh[tid] - v;
    if (tid == SCAN_B - 1) g_bsum[blockIdx.x] = sh[tid];
}

__global__ void scan2_kernel() {
    __shared__ int sh[128];
    int tid = threadIdx.x;
    int v = (tid < SCAN_NB) ? g_bsum[tid] : 0;
    sh[tid] = v;
    __syncthreads();
    for (int off = 1; off < 128; off <<= 1) {
        int t = (tid >= off) ? sh[tid - off] : 0;
        __syncthreads();
        sh[tid] += t;
        __syncthreads();
    }
    if (tid < SCAN_NB) g_boff[tid] = sh[tid] - v;
}

__global__ void scan3_kernel(int E) {
    int i = blockIdx.x * blockDim.x + threadIdx.x;
    if (i < N_NODES) {
        int off = g_off[i] + g_boff[i / SCAN_B];
        g_off[i] = off;
        g_cursor[i] = off;
        g_norm[i] = 1.0f / fmaxf((float)g_deg_src[i], 1.0f);
    }
    if (i == 0) g_off[N_NODES] = E;
}

__global__ void scatter_kernel(const int* __restrict__ src, const int* __restrict__ dst, int E) {
    int i = blockIdx.x * blockDim.x + threadIdx.x;
    if (i < E) {
        int pos = atomicAdd(&g_cursor[dst[i]], 1);
        g_csr[pos] = src[i];
    }
}

// ---------------------------------------------------------------------------
// Weight preprocessing: transpose to [N, K] and split fp32 -> bf16 hi/lo
// ---------------------------------------------------------------------------
__global__ void pre_w1_kernel(const float* __restrict__ W) {   // W: [256, 128]
    int i = blockIdx.x * blockDim.x + threadIdx.x;
    if (i < IN_F * HID) {
        int k = i / HID, n = i % HID;
        float w = W[i];
        __nv_bfloat16 hi = __float2bfloat16_rn(w);
        float lo = w - __bfloat162float(hi);
        g_w1hi[n * IN_F + k] = hi;
        g_w1lo[n * IN_F + k] = __float2bfloat16_rn(lo);
    }
}

__global__ void pre_w2_kernel(const float* __restrict__ Wmu, const float* __restrict__ Wls) {
    int i = blockIdx.x * blockDim.x + threadIdx.x;   // over 128*128 in [k][n] order
    if (i < HID * HID) {
        int k = i / HID, n = i % HID;
        float w = (n < 64) ? Wmu[k * OUT_F + n] : Wls[k * OUT_F + (n - 64)];
        __nv_bfloat16 hi = __float2bfloat16_rn(w);
        float lo = w - __bfloat162float(hi);
        g_w2hi[n * HID + k] = hi;
        g_w2lo[n * HID + k] = __float2bfloat16_rn(lo);
    }
}

// ---------------------------------------------------------------------------
// wmma split-bf16 GEMM: out[r,:] = (A[r,:] @ W) * norm[r], W via [N,K] hi/lo.
// CTA: 128 rows x 128 cols, 8 warps, warp w owns rows [16w, 16w+16).
// K chunks of 32; A fp32 -> hi/lo bf16 conversion fused into smem staging.
// D = Ahi*Bhi + Ahi*Blo + Alo*Bhi (fp32 accum) ~ fp32-grade accuracy.
// ---------------------------------------------------------------------------
#define LDM 40   // bf16 elems per staged row (16-pad; mult of 8 for wmma ldm)

template <int KT, bool FROM_ACC, bool USE_W2>
__global__ __launch_bounds__(256, 2)
void wmma_gemm_kernel(const float* __restrict__ Aext) {
    __shared__ __align__(16) __nv_bfloat16 sAhi[128 * LDM];
    __shared__ __align__(16) __nv_bfloat16 sAlo[128 * LDM];
    __shared__ __align__(16) __nv_bfloat16 sBhi[128 * LDM];
    __shared__ __align__(16) __nv_bfloat16 sBlo[128 * LDM];

    const float* Asrc = FROM_ACC ? g_acc : Aext;
    const __nv_bfloat16* Whi = USE_W2 ? g_w2hi : g_w1hi;
    const __nv_bfloat16* Wlo = USE_W2 ? g_w2lo : g_w1lo;

    const int tid = threadIdx.x;
    const int wid = tid >> 5;
    const int lane = tid & 31;
    const int row0 = blockIdx.x * 128;

    wmma::fragment<wmma::accumulator, 16, 16, 16, float> acc[8];
#pragma unroll
    for (int i = 0; i < 8; i++) wmma::fill_fragment(acc[i], 0.f);

#pragma unroll 1
    for (int k0 = 0; k0 < KT; k0 += 32) {
        __syncthreads();
        // Stage A: 128 rows x 32 k fp32 -> split bf16. 4 float4 per thread.
#pragma unroll
        for (int p = tid; p < 1024; p += 256) {
            int r = p >> 3;
            int kk = (p & 7) << 2;
            int grow = row0 + r;
            float4 v = make_float4(0.f, 0.f, 0.f, 0.f);
            if (grow < N_NODES)
                v = *(const float4*)(Asrc + (size_t)grow * KT + k0 + kk);
            float hx = __bfloat162float(__float2bfloat16_rn(v.x));
            float hy = __bfloat162float(__float2bfloat16_rn(v.y));
            float hz = __bfloat162float(__float2bfloat16_rn(v.z));
            float hw = __bfloat162float(__float2bfloat16_rn(v.w));
            uint2 hi = make_uint2(pack_bf16x2(v.x, v.y), pack_bf16x2(v.z, v.w));
            uint2 lo = make_uint2(pack_bf16x2(v.x - hx, v.y - hy),
                                  pack_bf16x2(v.z - hz, v.w - hw));
            *(uint2*)(sAhi + r * LDM + kk) = hi;
            *(uint2*)(sAlo + r * LDM + kk) = lo;
        }
        // Stage B: 128 n-rows x 32 k bf16 hi/lo. uint4 global -> 2x uint2 smem.
#pragma unroll
        for (int p = tid; p < 512; p += 256) {
            int n = p >> 2;
            int kk = (p & 3) << 3;
            size_t gsrc = (size_t)n * KT + k0 + kk;
            uint4 vh = *(const uint4*)(Whi + gsrc);
            uint4 vl = *(const uint4*)(Wlo + gsrc);
            *(uint2*)(sBhi + n * LDM + kk)     = make_uint2(vh.x, vh.y);
            *(uint2*)(sBhi + n * LDM + kk + 4) = make_uint2(vh.z, vh.w);
            *(uint2*)(sBlo + n * LDM + kk)     = make_uint2(vl.x, vl.y);
            *(uint2*)(sBlo + n * LDM + kk + 4) = make_uint2(vl.z, vl.w);
        }
        __syncthreads();

        const __nv_bfloat16* aphi = sAhi + wid * 16 * LDM;
        const __nv_bfloat16* aplo = sAlo + wid * 16 * LDM;
#pragma unroll
        for (int ks = 0; ks < 2; ks++) {
            wmma::fragment<wmma::matrix_a, 16, 16, 16, __nv_bfloat16, wmma::row_major> ahi, alo;
            wmma::load_matrix_sync(ahi, aphi + ks * 16, LDM);
            wmma::load_matrix_sync(alo, aplo + ks * 16, LDM);
#pragma unroll
            for (int nt = 0; nt < 8; nt++) {
                wmma::fragment<wmma::matrix_b, 16, 16, 16, __nv_bfloat16, wmma::col_major> bhi, blo;
                wmma::load_matrix_sync(bhi, sBhi + nt * 16 * LDM + ks * 16, LDM);
                wmma::load_matrix_sync(blo, sBlo + nt * 16 * LDM + ks * 16, LDM);
                wmma::mma_sync(acc[nt], ahi, bhi, acc[nt]);
                wmma::mma_sync(acc[nt], ahi, blo, acc[nt]);
                wmma::mma_sync(acc[nt], alo, bhi, acc[nt]);
            }
        }
    }

    // Epilogue: bounce each 16x16 frag through smem (reuse sAhi), scale by norm.
    __syncthreads();
    float* epi = reinterpret_cast<float*>(sAhi) + wid * 256;
    const int r = lane >> 1;
    const int c = (lane & 1) << 3;
    const int grow = row0 + wid * 16 + r;
    const float nv = (grow < N_NODES) ? g_norm[grow] : 0.f;
#pragma unroll
    for (int nt = 0; nt < 8; nt++) {
        wmma::store_matrix_sync(epi, acc[nt], 16, wmma::mem_row_major);
        __syncwarp();
        if (grow < N_NODES) {
            float4 v0 = *(float4*)(epi + r * 16 + c);
            float4 v1 = *(float4*)(epi + r * 16 + c + 4);
            v0.x *= nv; v0.y *= nv; v0.z *= nv; v0.w *= nv;
            v1.x *= nv; v1.y *= nv; v1.z *= nv; v1.w *= nv;
            *(float4*)(g_msg + (size_t)grow * HID + nt * 16 + c)     = v0;
            *(float4*)(g_msg + (size_t)grow * HID + nt * 16 + c + 4) = v1;
        }
        __syncwarp();
    }
}

// ---------------------------------------------------------------------------
// CSR aggregation (unchanged from R3)
// ---------------------------------------------------------------------------
__device__ __forceinline__ float4 warp_gather_sum(int n, int lane) {
    int beg = g_off[n];
    int end = g_off[n + 1];
    float4 acc = make_float4(0.f, 0.f, 0.f, 0.f);
    for (int base = beg; base < end; base += 32) {
        int idx = base + lane;
        int eid = (idx < end) ? g_csr[idx] : 0;
        int cnt = min(32, end - base);
        for (int k = 0; k < cnt; k++) {
            int s = __shfl_sync(0xffffffffu, eid, k);
            float4 v = *(const float4*)(g_msg + (size_t)s * HID + lane * 4);
            acc.x += v.x; acc.y += v.y; acc.z += v.z; acc.w += v.w;
        }
    }
    return acc;
}

__global__ void agg1_kernel(const float* __restrict__ bsh) {
    int n = (int)(((size_t)blockIdx.x * blockDim.x + threadIdx.x) >> 5);
    int lane = threadIdx.x & 31;
    if (n >= N_NODES) return;
    float4 acc = warp_gather_sum(n, lane);
    float4 bb = *(const float4*)(bsh + lane * 4);
    float4 o;
    o.x = fmaxf(acc.x + bb.x, 0.f);
    o.y = fmaxf(acc.y + bb.y, 0.f);
    o.z = fmaxf(acc.z + bb.z, 0.f);
    o.w = fmaxf(acc.w + bb.w, 0.f);
    *(float4*)(g_acc + (size_t)n * HID + lane * 4) = o;
}

__global__ void agg2_final_kernel(const float* __restrict__ noise,
                                  const float* __restrict__ bmu,
                                  const float* __restrict__ bls,
                                  float* __restrict__ out) {
    int n = (int)(((size_t)blockIdx.x * blockDim.x + threadIdx.x) >> 5);
    int lane = threadIdx.x & 31;
    if (n >= N_NODES) return;
    float4 acc = warp_gather_sum(n, lane);
    float4 other;
    other.x = __shfl_xor_sync(0xffffffffu, acc.x, 16);
    other.y = __shfl_xor_sync(0xffffffffu, acc.y, 16);
    other.z = __shfl_xor_sync(0xffffffffu, acc.z, 16);
    other.w = __shfl_xor_sync(0xffffffffu, acc.w, 16);
    if (lane < 16) {
        int j = lane * 4;
        float4 bm = *(const float4*)(bmu + j);
        float4 bl = *(const float4*)(bls + j);
        float4 nz = *(const float4*)(noise + (size_t)n * OUT_F + j);
        float4 o;
        o.x = acc.x + bm.x + nz.x * expf(other.x + bl.x);
        o.y = acc.y + bm.y + nz.y * expf(other.y + bl.y);
        o.z = acc.z + bm.z + nz.z * expf(other.z + bl.z);
        o.w = acc.w + bm.w + nz.w * expf(other.w + bl.w);
        *(float4*)(out + (size_t)n * OUT_F + j) = o;
    }
}

// ---------------------------------------------------------------------------
extern "C" void kernel_launch(void* const* d_in, const int* in_sizes, int n_in,
                              void* d_out, int out_size) {
    const float* feat  = (const float*)d_in[0];
    const float* Wsh   = (const float*)d_in[1];
    const float* bsh   = (const float*)d_in[2];
    const float* Wmu   = (const float*)d_in[3];
    const float* bmu   = (const float*)d_in[4];
    const float* Wls   = (const float*)d_in[5];
    const float* bls   = (const float*)d_in[6];
    const float* noise = (const float*)d_in[7];
    const int*   src   = (const int*)d_in[8];
    const int*   dst   = (const int*)d_in[9];
    const int E = in_sizes[8];
    float* out = (float*)d_out;

    const int agg_blocks  = (N_NODES * 32 + 255) / 256;   // warp per node
    const int gemm_blocks = (N_NODES + 127) / 128;        // 782

    zero_deg_kernel<<<(N_NODES + 255) / 256, 256>>>();
    hist_kernel<<<(E + 255) / 256, 256>>>(src, dst, E);
    pre_w1_kernel<<<(IN_F * HID + 255) / 256, 256>>>(Wsh);
    pre_w2_kernel<<<(HID * HID + 255) / 256, 256>>>(Wmu, Wls);
    scan1_kernel<<<SCAN_NB, SCAN_B>>>();
    scan2_kernel<<<1, 128>>>();
    scan3_kernel<<<(N_NODES + 255) / 256, 256>>>(E);
    scatter_kernel<<<(E + 255) / 256, 256>>>(src, dst, E);
    wmma_gemm_kernel<IN_F, false, false><<<gemm_blocks, 256>>>(feat);
    agg1_kernel<<<agg_blocks, 256>>>(bsh);
    wmma_gemm_kernel<HID, true, true><<<gemm_blocks, 256>>>(nullptr);
    agg2_final_kernel<<<agg_blocks, 256>>>(noise, bmu, bls, out);
}